// round 14
// baseline (speedup 1.0000x reference)
#include <cuda_runtime.h>
#include <cuda_fp16.h>
#include <math.h>

#define NU    2560
#define NI    3584
#define NN    6144
#define E     64
#define E2    32
#define DQK   256
#define TOPK  5
#define TOPS  10
#define STRIDE 96

#define KB     128
#define JTHIRD 2048
#define CHUNK  64
#define NCHUNK (JTHIRD / CHUNK)
#define NCAND  (3 * TOPS)
#define APITCH 272
#define BBYTES (CHUNK * APITCH)
#define MPITCH 41

typedef unsigned long long u64;

__device__ float g_ego0[NN * E];
__device__ float g_ego1[NN * E];
__device__ float g_ego2[NN * E];
__device__ float g_z[NN * E];
__device__ float g_Q[NN * DQK];
__device__ float g_K[NN * DQK];
__device__ u64   g_WqT[E2 * DQK];
__device__ u64   g_WkT[E2 * DQK];
__device__ u64   g_WvT[E2 * DQK];
__device__ __align__(16) __half g_A[NN * KB];
__device__ __align__(16) __half g_B[NN * KB];
__device__ int   g_candi[NN * NCAND];
__device__ int   g_cntN[NN], g_cntA[NN];
__device__ int2  g_ellN[NN * STRIDE], g_ellA[NN * STRIDE];

__device__ __forceinline__ u64 ffma2(u64 a, u64 b, u64 c) {
    u64 d;
    asm("fma.rn.f32x2 %0, %1, %2, %3;" : "=l"(d) : "l"(a), "l"(b), "l"(c));
    return d;
}
__device__ __forceinline__ float2 up2(u64 v) {
    float2 r;
    asm("mov.b64 {%0, %1}, %2;" : "=f"(r.x), "=f"(r.y) : "l"(v));
    return r;
}
__device__ __forceinline__ unsigned s2u(const void* p) {
    unsigned a;
    asm("{ .reg .u64 t; cvta.to.shared.u64 t, %1; cvt.u32.u64 %0, t; }"
        : "=r"(a) : "l"(p));
    return a;
}
__device__ __forceinline__ void split2h(float a, __half& h, __half& l) {
    h = __float2half_rn(a);
    l = __float2half_rn(a - __half2float(h));
}
__device__ __forceinline__ void top_ins(float v, int j, float* tv, int* ti) {
    if (v > tv[TOPS - 1]) {
        tv[TOPS - 1] = v; ti[TOPS - 1] = j;
#pragma unroll
        for (int q = TOPS - 1; q > 0; q--) {
            if (tv[q] > tv[q - 1]) {
                float fv = tv[q]; tv[q] = tv[q - 1]; tv[q - 1] = fv;
                int fi = ti[q]; ti[q] = ti[q - 1]; ti[q - 1] = fi;
            }
        }
    }
}

// K1a (main stream): concat + ELL-N placement
__global__ void prep_main_kernel(const float* __restrict__ user,
                                 const float* __restrict__ item,
                                 const int* __restrict__ nr, const int* __restrict__ nc,
                                 const float* __restrict__ nv, int nnzN) {
    int gid = blockIdx.x * blockDim.x + threadIdx.x;
    const int T1 = NN * E, T2 = T1 + nnzN;
    if (gid < T1) {
        g_ego0[gid] = (gid < NU * E) ? user[gid] : item[gid - NU * E];
    } else if (gid < T2) {
        int i = gid - T1;
        int r = nr[i];
        int p = atomicAdd(&g_cntN[r], 1);
        g_ellN[r * STRIDE + p] = make_int2(nc[i], __float_as_int(nv[i]));
    }
}

// K1b (side stream): W transpose + ELL-A placement
__global__ void prep_side_kernel(const int* __restrict__ ar, const int* __restrict__ ac,
                                 const float* __restrict__ av, int nnzA,
                                 const float* __restrict__ Wq,
                                 const float* __restrict__ Wk,
                                 const float* __restrict__ Wv) {
    int gid = blockIdx.x * blockDim.x + threadIdx.x;
    const int T1 = 3 * E2 * DQK, T2 = T1 + nnzA;
    if (gid < T1) {
        int m = gid / (E2 * DQK);
        int rem = gid - m * (E2 * DQK);
        int i = rem / DQK, d = rem - (rem / DQK) * DQK;
        const u64* src = (const u64*)(m == 0 ? Wq : (m == 1 ? Wk : Wv));
        u64* dst = (m == 0 ? g_WqT : (m == 1 ? g_WkT : g_WvT));
        dst[i * DQK + d] = src[d * E2 + i];
    } else if (gid < T2) {
        int i = gid - T1;
        int r = ar[i];
        int p = atomicAdd(&g_cntA[r], 1);
        g_ellA[r * STRIDE + p] = make_int2(ac[i], __float_as_int(av[i]));
    }
}

// flat int2 ELL gather, unroll-8 (R12-proven shape)
__device__ __forceinline__ float gather_row(const int* __restrict__ cnt,
                                            const int2* __restrict__ ell,
                                            const float* __restrict__ x,
                                            int r, int e) {
    int j0 = r * STRIDE, j1 = j0 + cnt[r];
    float acc = 0.0f;
    int j = j0;
    for (; j + 8 <= j1; j += 8) {
        int2 cv[8]; float xv[8];
#pragma unroll
        for (int u = 0; u < 8; u++) cv[u] = __ldg(&ell[j + u]);
#pragma unroll
        for (int u = 0; u < 8; u++) xv[u] = __ldg(&x[cv[u].x * E + e]);
#pragma unroll
        for (int u = 0; u < 8; u++) acc += __int_as_float(cv[u].y) * xv[u];
    }
    for (; j < j1; j++) {
        int2 cv = __ldg(&ell[j]);
        acc += __int_as_float(cv.y) * __ldg(&x[cv.x * E + e]);
    }
    return acc;
}

// K2: ego1 = A_norm @ ego0
__global__ void __launch_bounds__(256) gather1_kernel() {
    int w = (blockIdx.x * blockDim.x + threadIdx.x) >> 5;
    int e = (w & 1) * 32 + (threadIdx.x & 31);
    int r = w >> 1;
    g_ego1[r * E + e] = gather_row(g_cntN, g_ellN, g_ego0, r, e);
}

// K3: ego2 = A_norm @ ego1 ; mean out ; B split {eh, el}
__global__ void __launch_bounds__(256) gather2_kernel(float* __restrict__ dout) {
    int w = (blockIdx.x * blockDim.x + threadIdx.x) >> 5;
    int e = (w & 1) * 32 + (threadIdx.x & 31);
    int r = w >> 1;
    float eg2 = gather_row(g_cntN, g_ellN, g_ego1, r, e);
    g_ego2[r * E + e] = eg2;
    dout[r * E + e] = 0.5f * (g_ego0[r * E + e] + g_ego1[r * E + e]);
    __half h, l;
    split2h(eg2, h, l);
    __half* b = &g_B[r * KB + e];
    b[0] = h; b[64] = l;
}

// K4: z = ego2 + 0.5*A@ego2 ; store z ; A split {zh, zh}
__global__ void __launch_bounds__(256) gatherA_kernel() {
    int w = (blockIdx.x * blockDim.x + threadIdx.x) >> 5;
    int e = (w & 1) * 32 + (threadIdx.x & 31);
    int r = w >> 1;
    float z = 0.5f * gather_row(g_cntA, g_ellA, g_ego2, r, e)
            + g_ego2[r * E + e];
    g_z[r * E + e] = z;
    __half h = __float2half_rn(z);
    __half* a = &g_A[r * KB + e];
    a[0] = h; a[64] = h;
}

// K5 (side stream): Q/K projection — 192 blocks x 32 rows
__global__ void __launch_bounds__(256, 1) qk_kernel(const float* __restrict__ bq,
                                                    const float* __restrict__ bk) {
    __shared__ u64 xs[32 * E2];
    int t = threadIdx.x;
    u64 wq[E2], wk[E2];
#pragma unroll
    for (int i = 0; i < E2; i++) { wq[i] = g_WqT[i * DQK + t]; wk[i] = g_WkT[i * DQK + t]; }
    float rbq = bq[t], rbk = bk[t];
    const u64* eg = (const u64*)g_ego2;
    int r0 = blockIdx.x * 32;
    for (int i = t; i < 32 * E2; i += 256) xs[i] = eg[r0 * E2 + i];
    __syncthreads();
    for (int rr = 0; rr < 32; rr++) {
        const ulonglong2* xp = (const ulonglong2*)&xs[rr * E2];
        u64 aq = 0ULL, ak = 0ULL;
#pragma unroll
        for (int e2 = 0; e2 < E2; e2 += 2) {
            ulonglong2 xv = xp[e2 >> 1];
            aq = ffma2(wq[e2], xv.x, aq);
            ak = ffma2(wk[e2], xv.x, ak);
            aq = ffma2(wq[e2 + 1], xv.y, aq);
            ak = ffma2(wk[e2 + 1], xv.y, ak);
        }
        float2 q2 = up2(aq), k2 = up2(ak);
        g_Q[(r0 + rr) * DQK + t] = q2.x + q2.y + rbq;
        g_K[(r0 + rr) * DQK + t] = k2.x + k2.y + rbk;
    }
}

// K6: mma.sync fp16 approx sim (K=128) + per-row top-10 (per j-third)
__global__ void __launch_bounds__(256, 1) simtopk_mma_kernel() {
    extern __shared__ char sm[];
    unsigned sA = s2u(sm);
    unsigned sB0 = sA + 128 * APITCH;
    int tid = threadIdx.x, w = tid >> 5, lane = tid & 31;
    int rg = blockIdx.x / 3, jthird = blockIdx.x - rg * 3;
    int r0 = rg * 128, jb0 = jthird * JTHIRD;

    {
        unsigned dst = sB0;
        const char* src = (const char*)g_B + (size_t)jb0 * (KB * 2);
        for (int i = tid; i < CHUNK * 16; i += 256) {
            int r = i >> 4, c = i & 15;
            asm volatile("cp.async.cg.shared.global [%0], [%1], 16;"
                         :: "r"(dst + r * APITCH + c * 16), "l"(src + r * (KB * 2) + c * 16));
        }
        asm volatile("cp.async.commit_group;");
    }
    {
        const u64* asrc = (const u64*)(g_A + (size_t)r0 * KB);
        for (int i = tid; i < 128 * 32; i += 256) {
            int r = i >> 5, c = i & 31;
            *(u64*)(sm + r * APITCH + c * 8) = asrc[i];
        }
    }
    __syncthreads();

    unsigned af[8][4];
    {
        unsigned ab = sA + (w * 16 + (lane & 15)) * APITCH + ((lane >> 4) << 4);
#pragma unroll
        for (int kt = 0; kt < 8; kt++)
            asm volatile("ldmatrix.sync.aligned.m8n8.x4.shared.b16 {%0,%1,%2,%3}, [%4];"
                : "=r"(af[kt][0]), "=r"(af[kt][1]), "=r"(af[kt][2]), "=r"(af[kt][3])
                : "r"(ab + kt * 32));
    }

    float tv0[TOPS], tv1[TOPS]; int ti0[TOPS], ti1[TOPS];
#pragma unroll
    for (int q = 0; q < TOPS; q++) {
        tv0[q] = -3.0e38f; tv1[q] = -3.0e38f; ti0[q] = 0; ti1[q] = 0;
    }

    for (int cc = 0; cc < NCHUNK; cc++) {
        if (cc + 1 < NCHUNK) {
            unsigned dst = sB0 + ((cc + 1) & 1) * BBYTES;
            const char* src = (const char*)g_B + (size_t)(jb0 + (cc + 1) * CHUNK) * (KB * 2);
            for (int i = tid; i < CHUNK * 16; i += 256) {
                int r = i >> 4, c = i & 15;
                asm volatile("cp.async.cg.shared.global [%0], [%1], 16;"
                             :: "r"(dst + r * APITCH + c * 16), "l"(src + r * (KB * 2) + c * 16));
            }
            asm volatile("cp.async.commit_group;");
            asm volatile("cp.async.wait_group 1;");
        } else {
            asm volatile("cp.async.wait_group 0;");
        }
        __syncthreads();
        unsigned sBc = sB0 + (cc & 1) * BBYTES;
        int j0 = jb0 + cc * CHUNK;
        for (int jt = 0; jt < 8; jt += 2) {
            float dA0 = 0, dA1 = 0, dA2 = 0, dA3 = 0;
            float dB0 = 0, dB1 = 0, dB2 = 0, dB3 = 0;
            unsigned ba = sBc + (jt * 8 + (lane & 7)) * APITCH + ((lane >> 3) & 1) * 16;
            unsigned bb = ba + 8 * APITCH;
#pragma unroll
            for (int kt = 0; kt < 8; kt++) {
                unsigned p0, p1, q0, q1;
                asm volatile("ldmatrix.sync.aligned.m8n8.x2.shared.b16 {%0,%1}, [%2];"
                             : "=r"(p0), "=r"(p1) : "r"(ba + kt * 32));
                asm volatile("ldmatrix.sync.aligned.m8n8.x2.shared.b16 {%0,%1}, [%2];"
                             : "=r"(q0), "=r"(q1) : "r"(bb + kt * 32));
                asm volatile("mma.sync.aligned.m16n8k16.row.col.f32.f16.f16.f32 "
                    "{%0,%1,%2,%3}, {%4,%5,%6,%7}, {%8,%9}, {%0,%1,%2,%3};"
                    : "+f"(dA0), "+f"(dA1), "+f"(dA2), "+f"(dA3)
                    : "r"(af[kt][0]), "r"(af[kt][1]), "r"(af[kt][2]), "r"(af[kt][3]),
                      "r"(p0), "r"(p1));
                asm volatile("mma.sync.aligned.m16n8k16.row.col.f32.f16.f16.f32 "
                    "{%0,%1,%2,%3}, {%4,%5,%6,%7}, {%8,%9}, {%0,%1,%2,%3};"
                    : "+f"(dB0), "+f"(dB1), "+f"(dB2), "+f"(dB3)
                    : "r"(af[kt][0]), "r"(af[kt][1]), "r"(af[kt][2]), "r"(af[kt][3]),
                      "r"(q0), "r"(q1));
            }
            int jcA = j0 + jt * 8 + (lane & 3) * 2;
            int jcB = jcA + 8;
            top_ins(dA0, jcA, tv0, ti0);     top_ins(dA1, jcA + 1, tv0, ti0);
            top_ins(dA2, jcA, tv1, ti1);     top_ins(dA3, jcA + 1, tv1, ti1);
            top_ins(dB0, jcB, tv0, ti0);     top_ins(dB1, jcB + 1, tv0, ti0);
            top_ins(dB2, jcB, tv1, ti1);     top_ins(dB3, jcB + 1, tv1, ti1);
        }
        __syncthreads();
    }

    float* mv = (float*)sm;
    int*   mi = (int*)(sm + 128 * MPITCH * 4);
    int rb = w * 16 + (lane >> 2);
    int slot = (lane & 3) * TOPS;
#pragma unroll
    for (int q = 0; q < TOPS; q++) {
        mv[rb * MPITCH + slot + q] = tv0[q];        mi[rb * MPITCH + slot + q] = ti0[q];
        mv[(rb + 8) * MPITCH + slot + q] = tv1[q];  mi[(rb + 8) * MPITCH + slot + q] = ti1[q];
    }
    __syncthreads();
    if (tid < 128) {
        for (int sel = 0; sel < TOPS; sel++) {
            float best = -3.2e38f; int bs = 0;
            for (int m = 0; m < 40; m++) {
                float vv = mv[tid * MPITCH + m];
                if (vv > best) { best = vv; bs = m; }
            }
            mv[tid * MPITCH + bs] = -3.2e38f;
            g_candi[(r0 + tid) * NCAND + jthird * TOPS + sel] = mi[tid * MPITCH + bs];
        }
    }
}

// K7: exact rescore (register top-5) + attention + V proj ; resets counters
__global__ void __launch_bounds__(256, 1) attn_kernel(const float* __restrict__ bv,
                                                      float* __restrict__ out_att) {
    __shared__ __align__(16) float ws[32 * E];
    __shared__ int exi[8][NCAND];
    int t = threadIdx.x, lane = t & 31, w = t >> 5;
    int n0 = blockIdx.x * 32;

    {
        int i = blockIdx.x * 256 + t;
        if (i < NN) g_cntN[i] = 0;
        else if (i < 2 * NN) g_cntA[i - NN] = 0;
    }

    for (int i = 0; i < 4; i++) {
        int nl = i * 8 + w;
        int n = n0 + nl;
        int cid = g_candi[n * NCAND + (lane < NCAND ? lane : 0)];
        if (lane < NCAND) exi[w][lane] = cid;
        __syncwarp();
        float zl0 = g_z[n * E + lane];
        float zl1 = g_z[n * E + lane + 32];
        float sv[NCAND];
#pragma unroll
        for (int m = 0; m < NCAND; m++) {
            int id = __shfl_sync(0xffffffffu, cid, m);
            const float* ep = &g_ego2[id * E];
            float s = zl0 * ep[lane] + zl1 * ep[lane + 32];
#pragma unroll
            for (int o = 16; o > 0; o >>= 1)
                s += __shfl_xor_sync(0xffffffffu, s, o);
            sv[m] = s;
        }
        int idx[TOPK];
        unsigned used = 0;
#pragma unroll
        for (int sel = 0; sel < TOPK; sel++) {
            float best = -3.2e38f; int bs = 0;
#pragma unroll
            for (int m = 0; m < NCAND; m++)
                if (!((used >> m) & 1u) && sv[m] > best) { best = sv[m]; bs = m; }
            used |= (1u << bs);
            idx[sel] = exi[w][bs];
        }
        float q[8];
#pragma unroll
        for (int j = 0; j < 8; j++) q[j] = g_Q[n * DQK + j * 32 + lane];
        float p[TOPK];
#pragma unroll
        for (int k = 0; k < TOPK; k++) {
            const float* kp = &g_K[idx[k] * DQK];
            float s = 0.0f;
#pragma unroll
            for (int j = 0; j < 8; j++) s += q[j] * kp[j * 32 + lane];
            p[k] = s;
        }
#pragma unroll
        for (int k = 0; k < TOPK; k++)
#pragma unroll
            for (int o = 16; o > 0; o >>= 1)
                p[k] += __shfl_xor_sync(0xffffffffu, p[k], o);
        float mx = -3.0e38f;
#pragma unroll
        for (int k = 0; k < TOPK; k++) { p[k] *= 0.0625f; mx = fmaxf(mx, p[k]); }
        float den = 0.0f;
#pragma unroll
        for (int k = 0; k < TOPK; k++) { p[k] = __expf(p[k] - mx); den += p[k]; }
        float inv = 1.0f / den;
        float a0 = 0.0f, a1 = 0.0f;
#pragma unroll
        for (int k = 0; k < TOPK; k++) {
            float a = p[k] * inv;
            const float* ep = &g_ego2[idx[k] * E];
            a0 += a * ep[lane];
            a1 += a * ep[lane + 32];
        }
        ws[nl * E + lane] = a0;
        ws[nl * E + lane + 32] = a1;
    }
    __syncthreads();
    u64 wv[E2];
#pragma unroll
    for (int i = 0; i < E2; i++) wv[i] = g_WvT[i * DQK + t];
    float rbv = bv[t];
    for (int rr = 0; rr < 32; rr++) {
        const ulonglong2* xp = (const ulonglong2*)&ws[rr * E];
        u64 av = 0ULL;
#pragma unroll
        for (int e2 = 0; e2 < E2; e2 += 2) {
            ulonglong2 xv = xp[e2 >> 1];
            av = ffma2(wv[e2], xv.x, av);
            av = ffma2(wv[e2 + 1], xv.y, av);
        }
        float2 fv = up2(av);
        out_att[(n0 + rr) * DQK + t] = fv.x + fv.y + rbv;
    }
}

extern "C" void kernel_launch(void* const* d_in, const int* in_sizes, int n_in,
                              void* d_out, int out_size) {
    const float* user = (const float*)d_in[0];
    const float* item = (const float*)d_in[1];
    const int* nr = (const int*)d_in[2];
    const int* nc = (const int*)d_in[3];
    const float* nv = (const float*)d_in[4];
    const int* ar = (const int*)d_in[5];
    const int* ac = (const int*)d_in[6];
    const float* av = (const float*)d_in[7];
    const float* Wq = (const float*)d_in[8];
    const float* bq = (const float*)d_in[9];
    const float* Wk = (const float*)d_in[10];
    const float* bk = (const float*)d_in[11];
    const float* Wv = (const float*)d_in[12];
    const float* bv = (const float*)d_in[13];
    int nnzN = in_sizes[2];
    int nnzA = in_sizes[5];
    float* out = (float*)d_out;

    const int TPB = 256;
    cudaStream_t s0 = 0;  // default (captured) stream
    cudaStream_t s1;
    cudaStreamCreateWithFlags(&s1, cudaStreamNonBlocking);
    cudaEvent_t evFork, evSidePrep, evG2, evQK;
    cudaEventCreateWithFlags(&evFork, cudaEventDisableTiming);
    cudaEventCreateWithFlags(&evSidePrep, cudaEventDisableTiming);
    cudaEventCreateWithFlags(&evG2, cudaEventDisableTiming);
    cudaEventCreateWithFlags(&evQK, cudaEventDisableTiming);

    // fork side stream into the capture
    cudaEventRecord(evFork, s0);
    cudaStreamWaitEvent(s1, evFork, 0);

    // side: W transpose + ELL-A placement
    int totS = 3 * E2 * DQK + nnzA;
    prep_side_kernel<<<(totS + TPB - 1) / TPB, TPB, 0, s1>>>(ar, ac, av, nnzA,
                                                             Wq, Wk, Wv);
    cudaEventRecord(evSidePrep, s1);

    // main: concat + ELL-N, then the serial gather chain
    int totM = NN * E + nnzN;
    prep_main_kernel<<<(totM + TPB - 1) / TPB, TPB, 0, s0>>>(user, item, nr, nc,
                                                             nv, nnzN);
    int gridG = (NN * 64) / TPB;
    gather1_kernel<<<gridG, TPB, 0, s0>>>();
    gather2_kernel<<<gridG, TPB, 0, s0>>>(out);
    cudaEventRecord(evG2, s0);

    // side: qk after ego2 ready (overlaps gatherA + sim on main)
    cudaStreamWaitEvent(s1, evG2, 0);
    qk_kernel<<<NN / 32, TPB, 0, s1>>>(bq, bk);
    cudaEventRecord(evQK, s1);

    // main: gatherA needs ELL-A from side
    cudaStreamWaitEvent(s0, evSidePrep, 0);
    gatherA_kernel<<<gridG, TPB, 0, s0>>>();

    int smem_mma = 128 * APITCH + 2 * BBYTES;   // 69632
    cudaFuncSetAttribute(simtopk_mma_kernel,
                         cudaFuncAttributeMaxDynamicSharedMemorySize, smem_mma);
    simtopk_mma_kernel<<<(NN / 128) * 3, TPB, smem_mma, s0>>>();

    // join: attn needs Q/K from side
    cudaStreamWaitEvent(s0, evQK, 0);
    attn_kernel<<<NN / 32, TPB, 0, s0>>>(bv, out + NN * E);
    // streams/events intentionally not destroyed: destroying capture
    // participants mid-capture invalidates the graph. kernel_launch is called
    // O(1) times (correctness + capture), so the leak is bounded.
}

// round 16
// speedup vs baseline: 1.6327x; 1.6327x over previous
#include <cuda_runtime.h>
#include <cuda_fp16.h>
#include <math.h>

#define NU    2560
#define NI    3584
#define NN    6144
#define E     64
#define E2    32
#define DQK   256
#define TOPK  5
#define TOPS  10
#define STRIDE 96

#define KB     128
#define JTHIRD 2048
#define CHUNK  64
#define NCHUNK (JTHIRD / CHUNK)
#define NCAND  (3 * TOPS)
#define APITCH 272
#define BBYTES (CHUNK * APITCH)
#define MPITCH 41
#define GRIDG  (NN * 64 / 256)   // 1536 gather blocks

typedef unsigned long long u64;

__device__ float g_ego0[NN * E];
__device__ float g_ego1[NN * E];
__device__ float g_ego2[NN * E];
__device__ float g_z[NN * E];
__device__ float g_Q[NN * DQK];
__device__ float g_K[NN * DQK];
__device__ u64   g_WqT[E2 * DQK];
__device__ u64   g_WkT[E2 * DQK];
__device__ u64   g_WvT[E2 * DQK];
__device__ __align__(16) __half g_A[NN * KB];
__device__ __align__(16) __half g_B[NN * KB];
__device__ int   g_candi[NN * NCAND];
__device__ int   g_cntN[NN], g_cntA[NN];
__device__ int2  g_ellN[NN * STRIDE], g_ellA[NN * STRIDE];

__device__ __forceinline__ u64 ffma2(u64 a, u64 b, u64 c) {
    u64 d;
    asm("fma.rn.f32x2 %0, %1, %2, %3;" : "=l"(d) : "l"(a), "l"(b), "l"(c));
    return d;
}
__device__ __forceinline__ float2 up2(u64 v) {
    float2 r;
    asm("mov.b64 {%0, %1}, %2;" : "=f"(r.x), "=f"(r.y) : "l"(v));
    return r;
}
__device__ __forceinline__ unsigned s2u(const void* p) {
    unsigned a;
    asm("{ .reg .u64 t; cvta.to.shared.u64 t, %1; cvt.u32.u64 %0, t; }"
        : "=r"(a) : "l"(p));
    return a;
}
__device__ __forceinline__ void split2h(float a, __half& h, __half& l) {
    h = __float2half_rn(a);
    l = __float2half_rn(a - __half2float(h));
}
__device__ __forceinline__ void top_ins(float v, int j, float* tv, int* ti) {
    if (v > tv[TOPS - 1]) {
        tv[TOPS - 1] = v; ti[TOPS - 1] = j;
#pragma unroll
        for (int q = TOPS - 1; q > 0; q--) {
            if (tv[q] > tv[q - 1]) {
                float fv = tv[q]; tv[q] = tv[q - 1]; tv[q - 1] = fv;
                int fi = ti[q]; ti[q] = ti[q - 1]; ti[q - 1] = fi;
            }
        }
    }
}

// K1: concat + W transpose + padded-ELL placement (int2-packed)
__global__ void prep_place_kernel(const float* __restrict__ user,
                                  const float* __restrict__ item,
                                  const int* __restrict__ nr, const int* __restrict__ nc,
                                  const float* __restrict__ nv, int nnzN,
                                  const int* __restrict__ ar, const int* __restrict__ ac,
                                  const float* __restrict__ av, int nnzA,
                                  const float* __restrict__ Wq,
                                  const float* __restrict__ Wk,
                                  const float* __restrict__ Wv) {
    int gid = blockIdx.x * blockDim.x + threadIdx.x;
    const int T1 = NN * E, T2 = T1 + 3 * E2 * DQK, T3 = T2 + nnzN, T4 = T3 + nnzA;
    if (gid < T1) {
        g_ego0[gid] = (gid < NU * E) ? user[gid] : item[gid - NU * E];
    } else if (gid < T2) {
        int idx = gid - T1;
        int m = idx / (E2 * DQK);
        int rem = idx - m * (E2 * DQK);
        int i = rem / DQK, d = rem - (rem / DQK) * DQK;
        const u64* src = (const u64*)(m == 0 ? Wq : (m == 1 ? Wk : Wv));
        u64* dst = (m == 0 ? g_WqT : (m == 1 ? g_WkT : g_WvT));
        dst[i * DQK + d] = src[d * E2 + i];
    } else if (gid < T3) {
        int i = gid - T2;
        int r = nr[i];
        int p = atomicAdd(&g_cntN[r], 1);
        if (p < STRIDE)  // defensive: max deg ~70 << 96 for this workload
            g_ellN[r * STRIDE + p] = make_int2(nc[i], __float_as_int(nv[i]));
    } else if (gid < T4) {
        int i = gid - T3;
        int r = ar[i];
        int p = atomicAdd(&g_cntA[r], 1);
        if (p < STRIDE)
            g_ellA[r * STRIDE + p] = make_int2(ac[i], __float_as_int(av[i]));
    }
}

// flat int2 ELL gather, unroll-8
__device__ __forceinline__ float gather_row(const int* __restrict__ cnt,
                                            const int2* __restrict__ ell,
                                            const float* __restrict__ x,
                                            int r, int e) {
    int j0 = r * STRIDE, j1 = j0 + min(cnt[r], STRIDE);
    float acc = 0.0f;
    int j = j0;
    for (; j + 8 <= j1; j += 8) {
        int2 cv[8]; float xv[8];
#pragma unroll
        for (int u = 0; u < 8; u++) cv[u] = __ldg(&ell[j + u]);
#pragma unroll
        for (int u = 0; u < 8; u++) xv[u] = __ldg(&x[cv[u].x * E + e]);
#pragma unroll
        for (int u = 0; u < 8; u++) acc += __int_as_float(cv[u].y) * xv[u];
    }
    for (; j < j1; j++) {
        int2 cv = __ldg(&ell[j]);
        acc += __int_as_float(cv.y) * __ldg(&x[cv.x * E + e]);
    }
    return acc;
}

// K2: ego1 = A_norm @ ego0
__global__ void __launch_bounds__(256) gather1_kernel() {
    int w = (blockIdx.x * blockDim.x + threadIdx.x) >> 5;
    int e = (w & 1) * 32 + (threadIdx.x & 31);
    int r = w >> 1;
    g_ego1[r * E + e] = gather_row(g_cntN, g_ellN, g_ego0, r, e);
}

// K3: ego2 = A_norm @ ego1 ; mean out ; B split {eh, el}
__global__ void __launch_bounds__(256) gather2_kernel(float* __restrict__ dout) {
    int w = (blockIdx.x * blockDim.x + threadIdx.x) >> 5;
    int e = (w & 1) * 32 + (threadIdx.x & 31);
    int r = w >> 1;
    float eg2 = gather_row(g_cntN, g_ellN, g_ego1, r, e);
    g_ego2[r * E + e] = eg2;
    dout[r * E + e] = 0.5f * (g_ego0[r * E + e] + g_ego1[r * E + e]);
    __half h, l;
    split2h(eg2, h, l);
    __half* b = &g_B[r * KB + e];
    b[0] = h; b[64] = l;
}

// K4: heterogeneous fused launch — blocks [0, GRIDG): gatherA ; rest: qk.
// Both depend only on ego2 (+ ELL-A / W transposes from K1) and are mutually
// independent; the HW co-schedules the latency-bound gather with FMA-bound qk.
__global__ void __launch_bounds__(256, 1) gatherA_qk_kernel(
        const float* __restrict__ bq, const float* __restrict__ bk) {
    __shared__ u64 xs[32 * E2];   // used by qk branch only (8 KB)
    int t = threadIdx.x;
    if (blockIdx.x < GRIDG) {
        // ---- gatherA: z = ego2 + 0.5*A@ego2 ; A split {zh, zh} ----
        int w = (blockIdx.x * 256 + t) >> 5;
        int e = (w & 1) * 32 + (t & 31);
        int r = w >> 1;
        float z = 0.5f * gather_row(g_cntA, g_ellA, g_ego2, r, e)
                + g_ego2[r * E + e];
        g_z[r * E + e] = z;
        __half h = __float2half_rn(z);
        __half* a = &g_A[r * KB + e];
        a[0] = h; a[64] = h;
    } else {
        // ---- qk: Q/K projection, 32 rows per block ----
        int b = blockIdx.x - GRIDG;
        u64 wq[E2], wk[E2];
#pragma unroll
        for (int i = 0; i < E2; i++) {
            wq[i] = g_WqT[i * DQK + t];
            wk[i] = g_WkT[i * DQK + t];
        }
        float rbq = bq[t], rbk = bk[t];
        const u64* eg = (const u64*)g_ego2;
        int r0 = b * 32;
        for (int i = t; i < 32 * E2; i += 256) xs[i] = eg[r0 * E2 + i];
        __syncthreads();
        for (int rr = 0; rr < 32; rr++) {
            const ulonglong2* xp = (const ulonglong2*)&xs[rr * E2];
            u64 aq = 0ULL, ak = 0ULL;
#pragma unroll
            for (int e2 = 0; e2 < E2; e2 += 2) {
                ulonglong2 xv = xp[e2 >> 1];
                aq = ffma2(wq[e2], xv.x, aq);
                ak = ffma2(wk[e2], xv.x, ak);
                aq = ffma2(wq[e2 + 1], xv.y, aq);
                ak = ffma2(wk[e2 + 1], xv.y, ak);
            }
            float2 q2 = up2(aq), k2 = up2(ak);
            g_Q[(r0 + rr) * DQK + t] = q2.x + q2.y + rbq;
            g_K[(r0 + rr) * DQK + t] = k2.x + k2.y + rbk;
        }
    }
}

// K5: mma.sync fp16 approx sim (K=128) + per-row top-10 (per j-third)
__global__ void __launch_bounds__(256, 1) simtopk_mma_kernel() {
    extern __shared__ char sm[];
    unsigned sA = s2u(sm);
    unsigned sB0 = sA + 128 * APITCH;
    int tid = threadIdx.x, w = tid >> 5, lane = tid & 31;
    int rg = blockIdx.x / 3, jthird = blockIdx.x - rg * 3;
    int r0 = rg * 128, jb0 = jthird * JTHIRD;

    {
        unsigned dst = sB0;
        const char* src = (const char*)g_B + (size_t)jb0 * (KB * 2);
        for (int i = tid; i < CHUNK * 16; i += 256) {
            int r = i >> 4, c = i & 15;
            asm volatile("cp.async.cg.shared.global [%0], [%1], 16;"
                         :: "r"(dst + r * APITCH + c * 16), "l"(src + r * (KB * 2) + c * 16));
        }
        asm volatile("cp.async.commit_group;");
    }
    {
        const u64* asrc = (const u64*)(g_A + (size_t)r0 * KB);
        for (int i = tid; i < 128 * 32; i += 256) {
            int r = i >> 5, c = i & 31;
            *(u64*)(sm + r * APITCH + c * 8) = asrc[i];
        }
    }
    __syncthreads();

    unsigned af[8][4];
    {
        unsigned ab = sA + (w * 16 + (lane & 15)) * APITCH + ((lane >> 4) << 4);
#pragma unroll
        for (int kt = 0; kt < 8; kt++)
            asm volatile("ldmatrix.sync.aligned.m8n8.x4.shared.b16 {%0,%1,%2,%3}, [%4];"
                : "=r"(af[kt][0]), "=r"(af[kt][1]), "=r"(af[kt][2]), "=r"(af[kt][3])
                : "r"(ab + kt * 32));
    }

    float tv0[TOPS], tv1[TOPS]; int ti0[TOPS], ti1[TOPS];
#pragma unroll
    for (int q = 0; q < TOPS; q++) {
        tv0[q] = -3.0e38f; tv1[q] = -3.0e38f; ti0[q] = 0; ti1[q] = 0;
    }

    for (int cc = 0; cc < NCHUNK; cc++) {
        if (cc + 1 < NCHUNK) {
            unsigned dst = sB0 + ((cc + 1) & 1) * BBYTES;
            const char* src = (const char*)g_B + (size_t)(jb0 + (cc + 1) * CHUNK) * (KB * 2);
            for (int i = tid; i < CHUNK * 16; i += 256) {
                int r = i >> 4, c = i & 15;
                asm volatile("cp.async.cg.shared.global [%0], [%1], 16;"
                             :: "r"(dst + r * APITCH + c * 16), "l"(src + r * (KB * 2) + c * 16));
            }
            asm volatile("cp.async.commit_group;");
            asm volatile("cp.async.wait_group 1;");
        } else {
            asm volatile("cp.async.wait_group 0;");
        }
        __syncthreads();
        unsigned sBc = sB0 + (cc & 1) * BBYTES;
        int j0 = jb0 + cc * CHUNK;
        for (int jt = 0; jt < 8; jt += 2) {
            float dA0 = 0, dA1 = 0, dA2 = 0, dA3 = 0;
            float dB0 = 0, dB1 = 0, dB2 = 0, dB3 = 0;
            unsigned ba = sBc + (jt * 8 + (lane & 7)) * APITCH + ((lane >> 3) & 1) * 16;
            unsigned bb = ba + 8 * APITCH;
#pragma unroll
            for (int kt = 0; kt < 8; kt++) {
                unsigned p0, p1, q0, q1;
                asm volatile("ldmatrix.sync.aligned.m8n8.x2.shared.b16 {%0,%1}, [%2];"
                             : "=r"(p0), "=r"(p1) : "r"(ba + kt * 32));
                asm volatile("ldmatrix.sync.aligned.m8n8.x2.shared.b16 {%0,%1}, [%2];"
                             : "=r"(q0), "=r"(q1) : "r"(bb + kt * 32));
                asm volatile("mma.sync.aligned.m16n8k16.row.col.f32.f16.f16.f32 "
                    "{%0,%1,%2,%3}, {%4,%5,%6,%7}, {%8,%9}, {%0,%1,%2,%3};"
                    : "+f"(dA0), "+f"(dA1), "+f"(dA2), "+f"(dA3)
                    : "r"(af[kt][0]), "r"(af[kt][1]), "r"(af[kt][2]), "r"(af[kt][3]),
                      "r"(p0), "r"(p1));
                asm volatile("mma.sync.aligned.m16n8k16.row.col.f32.f16.f16.f32 "
                    "{%0,%1,%2,%3}, {%4,%5,%6,%7}, {%8,%9}, {%0,%1,%2,%3};"
                    : "+f"(dB0), "+f"(dB1), "+f"(dB2), "+f"(dB3)
                    : "r"(af[kt][0]), "r"(af[kt][1]), "r"(af[kt][2]), "r"(af[kt][3]),
                      "r"(q0), "r"(q1));
            }
            int jcA = j0 + jt * 8 + (lane & 3) * 2;
            int jcB = jcA + 8;
            top_ins(dA0, jcA, tv0, ti0);     top_ins(dA1, jcA + 1, tv0, ti0);
            top_ins(dA2, jcA, tv1, ti1);     top_ins(dA3, jcA + 1, tv1, ti1);
            top_ins(dB0, jcB, tv0, ti0);     top_ins(dB1, jcB + 1, tv0, ti0);
            top_ins(dB2, jcB, tv1, ti1);     top_ins(dB3, jcB + 1, tv1, ti1);
        }
        __syncthreads();
    }

    float* mv = (float*)sm;
    int*   mi = (int*)(sm + 128 * MPITCH * 4);
    int rb = w * 16 + (lane >> 2);
    int slot = (lane & 3) * TOPS;
#pragma unroll
    for (int q = 0; q < TOPS; q++) {
        mv[rb * MPITCH + slot + q] = tv0[q];        mi[rb * MPITCH + slot + q] = ti0[q];
        mv[(rb + 8) * MPITCH + slot + q] = tv1[q];  mi[(rb + 8) * MPITCH + slot + q] = ti1[q];
    }
    __syncthreads();
    if (tid < 128) {
        for (int sel = 0; sel < TOPS; sel++) {
            float best = -3.2e38f; int bs = 0;
            for (int m = 0; m < 40; m++) {
                float vv = mv[tid * MPITCH + m];
                if (vv > best) { best = vv; bs = m; }
            }
            mv[tid * MPITCH + bs] = -3.2e38f;
            g_candi[(r0 + tid) * NCAND + jthird * TOPS + sel] = mi[tid * MPITCH + bs];
        }
    }
}

// K6: exact rescore (register top-5) + attention + V proj ; resets counters
__global__ void __launch_bounds__(256, 1) attn_kernel(const float* __restrict__ bv,
                                                      float* __restrict__ out_att) {
    __shared__ __align__(16) float ws[32 * E];
    __shared__ int exi[8][NCAND];
    int t = threadIdx.x, lane = t & 31, w = t >> 5;
    int n0 = blockIdx.x * 32;

    {
        int i = blockIdx.x * 256 + t;
        if (i < NN) g_cntN[i] = 0;
        else if (i < 2 * NN) g_cntA[i - NN] = 0;
    }

    for (int i = 0; i < 4; i++) {
        int nl = i * 8 + w;
        int n = n0 + nl;
        int cid = g_candi[n * NCAND + (lane < NCAND ? lane : 0)];
        if (lane < NCAND) exi[w][lane] = cid;
        __syncwarp();
        float zl0 = g_z[n * E + lane];
        float zl1 = g_z[n * E + lane + 32];
        float sv[NCAND];
#pragma unroll
        for (int m = 0; m < NCAND; m++) {
            int id = __shfl_sync(0xffffffffu, cid, m);
            const float* ep = &g_ego2[id * E];
            float s = zl0 * ep[lane] + zl1 * ep[lane + 32];
#pragma unroll
            for (int o = 16; o > 0; o >>= 1)
                s += __shfl_xor_sync(0xffffffffu, s, o);
            sv[m] = s;
        }
        int idx[TOPK];
        unsigned used = 0;
#pragma unroll
        for (int sel = 0; sel < TOPK; sel++) {
            float best = -3.2e38f; int bs = 0;
#pragma unroll
            for (int m = 0; m < NCAND; m++)
                if (!((used >> m) & 1u) && sv[m] > best) { best = sv[m]; bs = m; }
            used |= (1u << bs);
            idx[sel] = exi[w][bs];
        }
        float q[8];
#pragma unroll
        for (int j = 0; j < 8; j++) q[j] = g_Q[n * DQK + j * 32 + lane];
        float p[TOPK];
#pragma unroll
        for (int k = 0; k < TOPK; k++) {
            const float* kp = &g_K[idx[k] * DQK];
            float s = 0.0f;
#pragma unroll
            for (int j = 0; j < 8; j++) s += q[j] * kp[j * 32 + lane];
            p[k] = s;
        }
#pragma unroll
        for (int k = 0; k < TOPK; k++)
#pragma unroll
            for (int o = 16; o > 0; o >>= 1)
                p[k] += __shfl_xor_sync(0xffffffffu, p[k], o);
        float mx = -3.0e38f;
#pragma unroll
        for (int k = 0; k < TOPK; k++) { p[k] *= 0.0625f; mx = fmaxf(mx, p[k]); }
        float den = 0.0f;
#pragma unroll
        for (int k = 0; k < TOPK; k++) { p[k] = __expf(p[k] - mx); den += p[k]; }
        float inv = 1.0f / den;
        float a0 = 0.0f, a1 = 0.0f;
#pragma unroll
        for (int k = 0; k < TOPK; k++) {
            float a = p[k] * inv;
            const float* ep = &g_ego2[idx[k] * E];
            a0 += a * ep[lane];
            a1 += a * ep[lane + 32];
        }
        ws[nl * E + lane] = a0;
        ws[nl * E + lane + 32] = a1;
    }
    __syncthreads();
    u64 wv[E2];
#pragma unroll
    for (int i = 0; i < E2; i++) wv[i] = g_WvT[i * DQK + t];
    float rbv = bv[t];
    for (int rr = 0; rr < 32; rr++) {
        const ulonglong2* xp = (const ulonglong2*)&ws[rr * E];
        u64 av = 0ULL;
#pragma unroll
        for (int e2 = 0; e2 < E2; e2 += 2) {
            ulonglong2 xv = xp[e2 >> 1];
            av = ffma2(wv[e2], xv.x, av);
            av = ffma2(wv[e2 + 1], xv.y, av);
        }
        float2 fv = up2(av);
        out_att[(n0 + rr) * DQK + t] = fv.x + fv.y + rbv;
    }
}

extern "C" void kernel_launch(void* const* d_in, const int* in_sizes, int n_in,
                              void* d_out, int out_size) {
    const float* user = (const float*)d_in[0];
    const float* item = (const float*)d_in[1];
    const int* nr = (const int*)d_in[2];
    const int* nc = (const int*)d_in[3];
    const float* nv = (const float*)d_in[4];
    const int* ar = (const int*)d_in[5];
    const int* ac = (const int*)d_in[6];
    const float* av = (const float*)d_in[7];
    const float* Wq = (const float*)d_in[8];
    const float* bq = (const float*)d_in[9];
    const float* Wk = (const float*)d_in[10];
    const float* bk = (const float*)d_in[11];
    const float* Wv = (const float*)d_in[12];
    const float* bv = (const float*)d_in[13];
    int nnzN = in_sizes[2];
    int nnzA = in_sizes[5];
    float* out = (float*)d_out;

    const int TPB = 256;
    int total1 = NN * E + 3 * E2 * DQK + nnzN + nnzA;
    prep_place_kernel<<<(total1 + TPB - 1) / TPB, TPB>>>(
        user, item, nr, nc, nv, nnzN, ar, ac, av, nnzA, Wq, Wk, Wv);

    gather1_kernel<<<GRIDG, TPB>>>();
    gather2_kernel<<<GRIDG, TPB>>>(out);
    gatherA_qk_kernel<<<GRIDG + NN / 32, TPB>>>(bq, bk);

    int smem_mma = 128 * APITCH + 2 * BBYTES;   // 69632
    cudaFuncSetAttribute(simtopk_mma_kernel,
                         cudaFuncAttributeMaxDynamicSharedMemorySize, smem_mma);
    simtopk_mma_kernel<<<(NN / 128) * 3, TPB, smem_mma>>>();

    attn_kernel<<<NN / 32, TPB>>>(bv, out + NN * E);
}